// round 2
// baseline (speedup 1.0000x reference)
#include <cuda_runtime.h>
#include <cstdint>

// Problem constants
#define BQ   16
#define TT   1024
#define CC   512
#define MTOT (BQ * TT)      // 16384 rows (b,t)
#define C2   (2 * CC)       // 1024

// ---------------- scratch (device globals; no allocation allowed) -----------
__device__ float g_xn[(size_t)MTOT * CC];       // LN output            32 MB
__device__ float g_h1[(size_t)MTOT * C2];       // GEMM1+SiLU output    64 MB
__device__ float g_hc[(size_t)MTOT * C2];       // conv output          64 MB
__device__ float g_h2[(size_t)MTOT * CC];       // GLU+BN output        32 MB

// ---------------- helpers ---------------------------------------------------
__device__ __forceinline__ float tf32r(float x) {
    uint32_t u;
    asm("cvt.rna.tf32.f32 %0, %1;" : "=r"(u) : "f"(x));
    return __uint_as_float(u);
}

__device__ __forceinline__ void mma8(float (&d)[4], const uint32_t (&a)[4], const uint32_t (&b)[2]) {
    asm volatile(
        "mma.sync.aligned.m16n8k8.row.col.f32.tf32.tf32.f32 "
        "{%0,%1,%2,%3}, {%4,%5,%6,%7}, {%8,%9}, {%0,%1,%2,%3};\n"
        : "+f"(d[0]), "+f"(d[1]), "+f"(d[2]), "+f"(d[3])
        : "r"(a[0]), "r"(a[1]), "r"(a[2]), "r"(a[3]),
          "r"(b[0]), "r"(b[1]));
}

__device__ __forceinline__ float fsigmoid(float v) { return 1.f / (1.f + __expf(-v)); }

// ---------------- 1) LayerNorm ----------------------------------------------
__global__ void ln_kernel(const float* __restrict__ x,
                          const float* __restrict__ lg,
                          const float* __restrict__ lb) {
    int row = blockIdx.x;
    const float2* xin = (const float2*)(x + (size_t)row * CC);
    float2 v = xin[threadIdx.x];
    float s = v.x + v.y;
    float q = v.x * v.x + v.y * v.y;
    #pragma unroll
    for (int o = 16; o; o >>= 1) {
        s += __shfl_xor_sync(0xffffffffu, s, o);
        q += __shfl_xor_sync(0xffffffffu, q, o);
    }
    __shared__ float ss[8], sq[8];
    __shared__ float mu_s, rs_s;
    int w = threadIdx.x >> 5, l = threadIdx.x & 31;
    if (l == 0) { ss[w] = s; sq[w] = q; }
    __syncthreads();
    if (threadIdx.x == 0) {
        float S = 0.f, Q = 0.f;
        #pragma unroll
        for (int i = 0; i < 8; i++) { S += ss[i]; Q += sq[i]; }
        float mu = S * (1.f / CC);
        float var = Q * (1.f / CC) - mu * mu;
        mu_s = mu;
        rs_s = rsqrtf(var + 1e-5f);
    }
    __syncthreads();
    float mu = mu_s, rs = rs_s;
    int c = threadIdx.x * 2;
    float2 o;
    o.x = (v.x - mu) * rs * lg[c]     + lb[c];
    o.y = (v.y - mu) * rs * lg[c + 1] + lb[c + 1];
    ((float2*)(g_xn + (size_t)row * CC))[threadIdx.x] = o;
}

// ---------------- 2/5) GEMM:  C = act(A @ W^T + bias) -----------------------
// A: M x KD row-major.  W: N x KD row-major.  tile 128x64xK32, 8 warps.
// MODE 0: A = g_xn, C = g_h1 (ACT=silu).  MODE 1: A = g_h2, C = out param.
template <int ACT, int N, int MODE, int KD>
__global__ __launch_bounds__(256, 2)
void gemm_wt(const float* __restrict__ W, const float* __restrict__ bias,
             float* __restrict__ outParam) {
    __shared__ float As[128][36];   // A tile, row-major, stride 36 (bank-safe)
    __shared__ float Bs[64][36];    // W tile, n-major k-contig, stride 36

    const float* A    = (MODE == 0) ? g_xn : g_h2;
    float*       Cout = (MODE == 0) ? g_h1 : outParam;

    const int m0 = blockIdx.x * 128, n0 = blockIdx.y * 64;
    const int tid = threadIdx.x;
    const int lane = tid & 31, warp = tid >> 5;
    const int wm = warp & 3, wn = warp >> 2;      // 4x2 warp grid, 32x32 / warp
    const int g = lane >> 2, t = lane & 3;

    const int ar = tid >> 3, ac = (tid & 7) * 4;  // A staging coords
    float4 aR[4], bR[2];
    constexpr int KT = KD / 32;

    auto ldA = [&](int kt) {
        const float* Ap = A + (size_t)m0 * KD + kt * 32;
        #pragma unroll
        for (int i = 0; i < 4; i++)
            aR[i] = *(const float4*)(Ap + (size_t)(ar + i * 32) * KD + ac);
    };
    auto ldB = [&](int kt) {
        #pragma unroll
        for (int j = 0; j < 2; j++) {
            int ch = tid * 2 + j;
            int n = ch >> 3, kc = (ch & 7) * 4;
            bR[j] = *(const float4*)(W + (size_t)(n0 + n) * KD + kt * 32 + kc);
        }
    };
    auto stA = [&]() {
        #pragma unroll
        for (int i = 0; i < 4; i++) {
            float4 v = aR[i];
            *(float4*)&As[ar + i * 32][ac] =
                make_float4(tf32r(v.x), tf32r(v.y), tf32r(v.z), tf32r(v.w));
        }
    };
    auto stB = [&]() {
        #pragma unroll
        for (int j = 0; j < 2; j++) {
            int ch = tid * 2 + j;
            int n = ch >> 3, kc = (ch & 7) * 4;
            float4 v = bR[j];
            *(float4*)&Bs[n][kc] =
                make_float4(tf32r(v.x), tf32r(v.y), tf32r(v.z), tf32r(v.w));
        }
    };

    float acc[2][4][4];
    #pragma unroll
    for (int mi = 0; mi < 2; mi++)
        #pragma unroll
        for (int ni = 0; ni < 4; ni++)
            #pragma unroll
            for (int j = 0; j < 4; j++) acc[mi][ni][j] = 0.f;

    auto comp = [&]() {
        #pragma unroll
        for (int ks = 0; ks < 4; ks++) {
            const int kb = ks * 8;
            uint32_t af[2][4];
            #pragma unroll
            for (int mi = 0; mi < 2; mi++) {
                int r0 = wm * 32 + mi * 16 + g;
                af[mi][0] = __float_as_uint(As[r0][kb + t]);
                af[mi][1] = __float_as_uint(As[r0 + 8][kb + t]);
                af[mi][2] = __float_as_uint(As[r0][kb + t + 4]);
                af[mi][3] = __float_as_uint(As[r0 + 8][kb + t + 4]);
            }
            uint32_t bf[4][2];
            #pragma unroll
            for (int ni = 0; ni < 4; ni++) {
                int c0 = wn * 32 + ni * 8 + g;
                bf[ni][0] = __float_as_uint(Bs[c0][kb + t]);
                bf[ni][1] = __float_as_uint(Bs[c0][kb + t + 4]);
            }
            #pragma unroll
            for (int mi = 0; mi < 2; mi++)
                #pragma unroll
                for (int ni = 0; ni < 4; ni++)
                    mma8(acc[mi][ni], af[mi], bf[ni]);
        }
    };

    ldA(0); ldB(0);
    #pragma unroll 1
    for (int kt = 0; kt < KT; ++kt) {
        stA(); stB();
        __syncthreads();
        if (kt + 1 < KT) { ldA(kt + 1); ldB(kt + 1); }
        comp();
        __syncthreads();
    }

    #pragma unroll
    for (int mi = 0; mi < 2; mi++) {
        int r0 = m0 + wm * 32 + mi * 16 + g;
        #pragma unroll
        for (int ni = 0; ni < 4; ni++) {
            int c0 = n0 + wn * 32 + ni * 8 + t * 2;
            #pragma unroll
            for (int j = 0; j < 4; j++) {
                int row = r0 + ((j >= 2) ? 8 : 0);
                int col = c0 + (j & 1);
                float v = acc[mi][ni][j] + bias[col];
                if (ACT == 1) v = v * fsigmoid(v);
                Cout[(size_t)row * N + col] = v;
            }
        }
    }
}

// ---------------- 3) Conv1d (K=5) as 5 accumulated GEMMs ---------------------
// out[m,o] = sum_{kc} sum_i g_h1[m + (kc-2), i] * w2[kc, i, o] + b2[o]
__global__ __launch_bounds__(256, 2)
void conv_gemm(const float* __restrict__ W2, const float* __restrict__ b2) {
    __shared__ float As[128][36];
    __shared__ float Bs[32][72];    // [k][n], stride 72 (bank-safe)

    const int m0 = blockIdx.x * 128, n0 = blockIdx.y * 64;
    const int bb = m0 >> 10, t0 = m0 & 1023;
    const int tid = threadIdx.x;
    const int lane = tid & 31, warp = tid >> 5;
    const int wm = warp & 3, wn = warp >> 2;
    const int g = lane >> 2, t = lane & 3;

    const int ar = tid >> 3, ac = (tid & 7) * 4;
    float4 aR[4], bR[2];

    auto ldA = [&](int it) {
        int kc = it >> 5, kt = it & 31;
        int shift = kc - 2;
        #pragma unroll
        for (int i = 0; i < 4; i++) {
            int r = ar + i * 32;
            int trow = t0 + r + shift;
            if (trow >= 0 && trow < TT)
                aR[i] = *(const float4*)(g_h1 +
                        ((size_t)(bb * TT + trow)) * C2 + kt * 32 + ac);
            else
                aR[i] = make_float4(0.f, 0.f, 0.f, 0.f);
        }
    };
    auto ldB = [&](int it) {
        int kc = it >> 5, kt = it & 31;
        const float* Wk = W2 + (size_t)kc * C2 * C2;
        #pragma unroll
        for (int j = 0; j < 2; j++) {
            int ch = tid * 2 + j;
            int k = ch >> 4, n = (ch & 15) * 4;
            bR[j] = *(const float4*)(Wk + (size_t)(kt * 32 + k) * C2 + n0 + n);
        }
    };
    auto stA = [&]() {
        #pragma unroll
        for (int i = 0; i < 4; i++) {
            float4 v = aR[i];
            *(float4*)&As[ar + i * 32][ac] =
                make_float4(tf32r(v.x), tf32r(v.y), tf32r(v.z), tf32r(v.w));
        }
    };
    auto stB = [&]() {
        #pragma unroll
        for (int j = 0; j < 2; j++) {
            int ch = tid * 2 + j;
            int k = ch >> 4, n = (ch & 15) * 4;
            float4 v = bR[j];
            *(float4*)&Bs[k][n] =
                make_float4(tf32r(v.x), tf32r(v.y), tf32r(v.z), tf32r(v.w));
        }
    };

    float acc[2][4][4];
    #pragma unroll
    for (int mi = 0; mi < 2; mi++)
        #pragma unroll
        for (int ni = 0; ni < 4; ni++)
            #pragma unroll
            for (int j = 0; j < 4; j++) acc[mi][ni][j] = 0.f;

    auto comp = [&]() {
        #pragma unroll
        for (int ks = 0; ks < 4; ks++) {
            const int kb = ks * 8;
            uint32_t af[2][4];
            #pragma unroll
            for (int mi = 0; mi < 2; mi++) {
                int r0 = wm * 32 + mi * 16 + g;
                af[mi][0] = __float_as_uint(As[r0][kb + t]);
                af[mi][1] = __float_as_uint(As[r0 + 8][kb + t]);
                af[mi][2] = __float_as_uint(As[r0][kb + t + 4]);
                af[mi][3] = __float_as_uint(As[r0 + 8][kb + t + 4]);
            }
            uint32_t bf[4][2];
            #pragma unroll
            for (int ni = 0; ni < 4; ni++) {
                int c0 = wn * 32 + ni * 8 + g;
                bf[ni][0] = __float_as_uint(Bs[kb + t][c0]);
                bf[ni][1] = __float_as_uint(Bs[kb + t + 4][c0]);
            }
            #pragma unroll
            for (int mi = 0; mi < 2; mi++)
                #pragma unroll
                for (int ni = 0; ni < 4; ni++)
                    mma8(acc[mi][ni], af[mi], bf[ni]);
        }
    };

    ldA(0); ldB(0);
    #pragma unroll 1
    for (int it = 0; it < 160; ++it) {     // 5 taps x 32 K-tiles
        stA(); stB();
        __syncthreads();
        if (it + 1 < 160) { ldA(it + 1); ldB(it + 1); }
        comp();
        __syncthreads();
    }

    #pragma unroll
    for (int mi = 0; mi < 2; mi++) {
        int r0 = m0 + wm * 32 + mi * 16 + g;
        #pragma unroll
        for (int ni = 0; ni < 4; ni++) {
            int c0 = n0 + wn * 32 + ni * 8 + t * 2;
            #pragma unroll
            for (int j = 0; j < 4; j++) {
                int row = r0 + ((j >= 2) ? 8 : 0);
                int col = c0 + (j & 1);
                g_hc[(size_t)row * C2 + col] = acc[mi][ni][j] + b2[col];
            }
        }
    }
}

// ---------------- 4) GLU + BatchNorm (inference) ----------------------------
__global__ void glu_bn(const float* __restrict__ bg, const float* __restrict__ bb_,
                       const float* __restrict__ bm, const float* __restrict__ bv) {
    int p = blockIdx.x * blockDim.x + threadIdx.x;   // float4 index
    int m = p >> 7;                                  // 128 float4 per row
    int c4 = (p & 127) * 4;
    float4 a  = *(const float4*)(g_hc + (size_t)m * C2 + c4);
    float4 gg = *(const float4*)(g_hc + (size_t)m * C2 + CC + c4);
    float4 o;
    {
        float s = bg[c4] * rsqrtf(bv[c4] + 1e-5f);
        o.x = (a.x * fsigmoid(gg.x) - bm[c4]) * s + bb_[c4];
    }
    {
        float s = bg[c4 + 1] * rsqrtf(bv[c4 + 1] + 1e-5f);
        o.y = (a.y * fsigmoid(gg.y) - bm[c4 + 1]) * s + bb_[c4 + 1];
    }
    {
        float s = bg[c4 + 2] * rsqrtf(bv[c4 + 2] + 1e-5f);
        o.z = (a.z * fsigmoid(gg.z) - bm[c4 + 2]) * s + bb_[c4 + 2];
    }
    {
        float s = bg[c4 + 3] * rsqrtf(bv[c4 + 3] + 1e-5f);
        o.w = (a.w * fsigmoid(gg.w) - bm[c4 + 3]) * s + bb_[c4 + 3];
    }
    *(float4*)(g_h2 + (size_t)m * CC + c4) = o;
}

// ---------------- launch -----------------------------------------------------
extern "C" void kernel_launch(void* const* d_in, const int* in_sizes, int n_in,
                              void* d_out, int out_size) {
    const float* x     = (const float*)d_in[0];
    const float* ln_g  = (const float*)d_in[1];
    const float* ln_b  = (const float*)d_in[2];
    const float* w1    = (const float*)d_in[3];
    const float* b1    = (const float*)d_in[4];
    const float* w2    = (const float*)d_in[5];
    const float* b2    = (const float*)d_in[6];
    const float* bn_g  = (const float*)d_in[7];
    const float* bn_b  = (const float*)d_in[8];
    const float* bn_m  = (const float*)d_in[9];
    const float* bn_v  = (const float*)d_in[10];
    const float* w3    = (const float*)d_in[11];
    const float* b3    = (const float*)d_in[12];
    float* out = (float*)d_out;

    ln_kernel<<<MTOT, 256>>>(x, ln_g, ln_b);
    gemm_wt<1, C2, 0, CC><<<dim3(MTOT / 128, C2 / 64), 256>>>(w1, b1, nullptr);
    conv_gemm<<<dim3(MTOT / 128, C2 / 64), 256>>>(w2, b2);
    glu_bn<<<(MTOT * CC / 4) / 256, 256>>>(bn_g, bn_b, bn_m, bn_v);
    gemm_wt<0, CC, 1, CC><<<dim3(MTOT / 128, CC / 64), 256>>>(w3, b3, out);
}

// round 4
// speedup vs baseline: 1.3298x; 1.3298x over previous
#include <cuda_runtime.h>
#include <cstdint>

// Problem constants
#define BQ   16
#define TT   1024
#define CC   512
#define MTOT (BQ * TT)      // 16384 rows (b,t)
#define C2   (2 * CC)       // 1024

// ---------------- scratch (device globals; no allocation allowed) -----------
__device__ float g_xn[(size_t)MTOT * CC];       // LN output            32 MB
__device__ float g_h1[(size_t)MTOT * C2];       // GEMM1+SiLU output    64 MB
__device__ float g_hc[(size_t)MTOT * C2];       // conv output          64 MB
__device__ float g_h2[(size_t)MTOT * CC];       // GLU+BN output        32 MB

// ---------------- helpers ---------------------------------------------------
__device__ __forceinline__ float tf32r(float x) {
    uint32_t u;
    asm("cvt.rna.tf32.f32 %0, %1;" : "=r"(u) : "f"(x));
    return __uint_as_float(u);
}
__device__ __forceinline__ uint32_t tf32u(float x) {
    uint32_t u;
    asm("cvt.rna.tf32.f32 %0, %1;" : "=r"(u) : "f"(x));
    return u;
}

__device__ __forceinline__ void mma8(float (&d)[4], const uint32_t (&a)[4], const uint32_t (&b)[2]) {
    asm volatile(
        "mma.sync.aligned.m16n8k8.row.col.f32.tf32.tf32.f32 "
        "{%0,%1,%2,%3}, {%4,%5,%6,%7}, {%8,%9}, {%0,%1,%2,%3};\n"
        : "+f"(d[0]), "+f"(d[1]), "+f"(d[2]), "+f"(d[3])
        : "r"(a[0]), "r"(a[1]), "r"(a[2]), "r"(a[3]),
          "r"(b[0]), "r"(b[1]));
}

__device__ __forceinline__ void cpa16(uint32_t dst, const float* src) {
    asm volatile("cp.async.cg.shared.global [%0], [%1], 16;\n" :: "r"(dst), "l"(src));
}
__device__ __forceinline__ void cpa16p(uint32_t dst, const float* src, bool pred) {
    int sz = pred ? 16 : 0;
    asm volatile("cp.async.cg.shared.global [%0], [%1], 16, %2;\n" :: "r"(dst), "l"(src), "r"(sz));
}
__device__ __forceinline__ void cp_commit() { asm volatile("cp.async.commit_group;\n"); }
__device__ __forceinline__ void cp_wait1() { asm volatile("cp.async.wait_group 1;\n"); }

__device__ __forceinline__ float fsigmoid(float v) { return 1.f / (1.f + __expf(-v)); }

// ---------------- 1) LayerNorm ----------------------------------------------
__global__ void ln_kernel(const float* __restrict__ x,
                          const float* __restrict__ lg,
                          const float* __restrict__ lb) {
    int row = blockIdx.x;
    const float2* xin = (const float2*)(x + (size_t)row * CC);
    float2 v = xin[threadIdx.x];
    float s = v.x + v.y;
    float q = v.x * v.x + v.y * v.y;
    #pragma unroll
    for (int o = 16; o; o >>= 1) {
        s += __shfl_xor_sync(0xffffffffu, s, o);
        q += __shfl_xor_sync(0xffffffffu, q, o);
    }
    __shared__ float ss[8], sq[8];
    __shared__ float mu_s, rs_s;
    int w = threadIdx.x >> 5, l = threadIdx.x & 31;
    if (l == 0) { ss[w] = s; sq[w] = q; }
    __syncthreads();
    if (threadIdx.x == 0) {
        float S = 0.f, Q = 0.f;
        #pragma unroll
        for (int i = 0; i < 8; i++) { S += ss[i]; Q += sq[i]; }
        float mu = S * (1.f / CC);
        float var = Q * (1.f / CC) - mu * mu;
        mu_s = mu;
        rs_s = rsqrtf(var + 1e-5f);
    }
    __syncthreads();
    float mu = mu_s, rs = rs_s;
    int c = threadIdx.x * 2;
    float2 o;
    o.x = (v.x - mu) * rs * lg[c]     + lb[c];
    o.y = (v.y - mu) * rs * lg[c + 1] + lb[c + 1];
    ((float2*)(g_xn + (size_t)row * CC))[threadIdx.x] = o;
}

// ---------------- 2/5) GEMM:  C = act(A @ W^T + bias) -----------------------
// Tile 128x128xK32, 8 warps (2x4), warp tile 64x32. 3-stage cp.async pipeline.
// A: M x KD row-major.  W: N x KD row-major (k-contiguous).
// MODE 0: A = g_xn, C = g_h1 (ACT=silu).  MODE 1: A = g_h2, C = out param.
template <int ACT, int N, int MODE, int KD>
__global__ __launch_bounds__(256)
void gemm_wt(const float* __restrict__ W, const float* __restrict__ bias,
             float* __restrict__ outParam) {
    extern __shared__ float sm[];
    constexpr int ASZ = 128 * 36;
    constexpr int BSZ = 128 * 36;
    float* AsB = sm;                 // 3 stages A
    float* BsB = sm + 3 * ASZ;       // 3 stages B
    constexpr int KT = KD / 32;

    const float* A    = (MODE == 0) ? g_xn : g_h2;
    float*       Cout = (MODE == 0) ? g_h1 : outParam;

    const int m0 = blockIdx.x * 128, n0 = blockIdx.y * 128;
    const int tid = threadIdx.x;
    const int lane = tid & 31, warp = tid >> 5;
    const int wm = warp & 1, wn = warp >> 1;      // 2x4 warp grid, 64x32 / warp
    const int g = lane >> 2, t = lane & 3;
    const int ar = tid >> 3, ac = (tid & 7) * 4;

    auto stage = [&](int s) {
        float* a = AsB + (s % 3) * ASZ;
        float* b = BsB + (s % 3) * BSZ;
        const float* Ap = A + (size_t)(m0 + ar) * KD + s * 32 + ac;
        #pragma unroll
        for (int i = 0; i < 4; i++) {
            uint32_t d = (uint32_t)__cvta_generic_to_shared(a + (ar + i * 32) * 36 + ac);
            cpa16(d, Ap + (size_t)(i * 32) * KD);
        }
        #pragma unroll
        for (int j = 0; j < 4; j++) {
            int n  = j * 32 + (tid >> 3);
            int kc = (tid & 7) * 4;
            uint32_t d = (uint32_t)__cvta_generic_to_shared(b + n * 36 + kc);
            cpa16(d, W + (size_t)(n0 + n) * KD + s * 32 + kc);
        }
        cp_commit();
    };

    float acc[4][4][4];
    #pragma unroll
    for (int mi = 0; mi < 4; mi++)
        #pragma unroll
        for (int ni = 0; ni < 4; ni++)
            #pragma unroll
            for (int j = 0; j < 4; j++) acc[mi][ni][j] = 0.f;

    auto comp = [&](int s) {
        const float* a = AsB + (s % 3) * ASZ;
        const float* b = BsB + (s % 3) * BSZ;
        #pragma unroll
        for (int ks = 0; ks < 4; ks++) {
            const int kb = ks * 8;
            uint32_t af[4][4];
            #pragma unroll
            for (int mi = 0; mi < 4; mi++) {
                int r0 = wm * 64 + mi * 16 + g;
                af[mi][0] = tf32u(a[r0 * 36 + kb + t]);
                af[mi][1] = tf32u(a[(r0 + 8) * 36 + kb + t]);
                af[mi][2] = tf32u(a[r0 * 36 + kb + t + 4]);
                af[mi][3] = tf32u(a[(r0 + 8) * 36 + kb + t + 4]);
            }
            uint32_t bf[4][2];
            #pragma unroll
            for (int ni = 0; ni < 4; ni++) {
                int c0 = wn * 32 + ni * 8 + g;
                bf[ni][0] = tf32u(b[c0 * 36 + kb + t]);
                bf[ni][1] = tf32u(b[c0 * 36 + kb + t + 4]);
            }
            #pragma unroll
            for (int mi = 0; mi < 4; mi++)
                #pragma unroll
                for (int ni = 0; ni < 4; ni++)
                    mma8(acc[mi][ni], af[mi], bf[ni]);
        }
    };

    stage(0);
    stage(1);
    #pragma unroll 1
    for (int kt = 0; kt < KT; ++kt) {
        cp_wait1();
        __syncthreads();
        if (kt + 2 < KT) stage(kt + 2);
        comp(kt);
    }

    #pragma unroll
    for (int mi = 0; mi < 4; mi++) {
        int r0 = m0 + wm * 64 + mi * 16 + g;
        #pragma unroll
        for (int ni = 0; ni < 4; ni++) {
            int c0 = n0 + wn * 32 + ni * 8 + t * 2;
            float2 v0, v1;
            v0.x = acc[mi][ni][0] + bias[c0];
            v0.y = acc[mi][ni][1] + bias[c0 + 1];
            v1.x = acc[mi][ni][2] + bias[c0];
            v1.y = acc[mi][ni][3] + bias[c0 + 1];
            if (ACT == 1) {
                v0.x *= fsigmoid(v0.x); v0.y *= fsigmoid(v0.y);
                v1.x *= fsigmoid(v1.x); v1.y *= fsigmoid(v1.y);
            }
            *(float2*)(Cout + (size_t)r0 * N + c0)       = v0;
            *(float2*)(Cout + (size_t)(r0 + 8) * N + c0) = v1;
        }
    }
}

// ---------------- 3) Conv1d (K=5) as 5 accumulated GEMMs ---------------------
// out[m,o] = sum_{kc} sum_i g_h1[m + (kc-2), i] * w2[kc, i, o] + b2[o]
// Tile 128x128, iteration s = kt*5 + kc, 3-stage cp.async pipeline.
__global__ __launch_bounds__(256)
void conv_gemm(const float* __restrict__ W2, const float* __restrict__ b2) {
    extern __shared__ float sm[];
    constexpr int ASZ = 128 * 36;     // A tile [row][k] stride 36
    constexpr int BSZ = 32 * 136;     // B tile [k][n]  stride 136
    float* AsB = sm;
    float* BsB = sm + 3 * ASZ;
    constexpr int NIT = 160;          // 32 K-tiles x 5 taps

    const int m0 = blockIdx.x * 128, n0 = blockIdx.y * 128;
    const int bb = m0 >> 10, t0 = m0 & 1023;
    const int tid = threadIdx.x;
    const int lane = tid & 31, warp = tid >> 5;
    const int wm = warp & 1, wn = warp >> 1;
    const int g = lane >> 2, t = lane & 3;
    const int ar = tid >> 3, ac = (tid & 7) * 4;

    auto stage = [&](int s) {
        int kt = s / 5;
        int kc = s - kt * 5;
        float* a = AsB + (s % 3) * ASZ;
        float* b = BsB + (s % 3) * BSZ;
        int shift = kc - 2;
        const float* Abase = g_h1 + (size_t)(bb * TT) * C2 + kt * 32 + ac;
        #pragma unroll
        for (int i = 0; i < 4; i++) {
            int trow = t0 + ar + i * 32 + shift;
            bool ok = (trow >= 0) && (trow < TT);
            int srow = ok ? trow : 0;
            uint32_t d = (uint32_t)__cvta_generic_to_shared(a + (ar + i * 32) * 36 + ac);
            cpa16p(d, Abase + (size_t)srow * C2, ok);
        }
        const float* Wk = W2 + (size_t)kc * C2 * C2 + (size_t)(kt * 32) * C2 + n0;
        #pragma unroll
        for (int j = 0; j < 4; j++) {
            int k  = j * 8 + (tid >> 5);
            int n4 = (tid & 31) * 4;
            uint32_t d = (uint32_t)__cvta_generic_to_shared(b + k * 136 + n4);
            cpa16(d, Wk + (size_t)k * C2 + n4);
        }
        cp_commit();
    };

    float acc[4][4][4];
    #pragma unroll
    for (int mi = 0; mi < 4; mi++)
        #pragma unroll
        for (int ni = 0; ni < 4; ni++)
            #pragma unroll
            for (int j = 0; j < 4; j++) acc[mi][ni][j] = 0.f;

    auto comp = [&](int s) {
        const float* a = AsB + (s % 3) * ASZ;
        const float* b = BsB + (s % 3) * BSZ;
        #pragma unroll
        for (int ks = 0; ks < 4; ks++) {
            const int kb = ks * 8;
            uint32_t af[4][4];
            #pragma unroll
            for (int mi = 0; mi < 4; mi++) {
                int r0 = wm * 64 + mi * 16 + g;
                af[mi][0] = tf32u(a[r0 * 36 + kb + t]);
                af[mi][1] = tf32u(a[(r0 + 8) * 36 + kb + t]);
                af[mi][2] = tf32u(a[r0 * 36 + kb + t + 4]);
                af[mi][3] = tf32u(a[(r0 + 8) * 36 + kb + t + 4]);
            }
            uint32_t bf[4][2];
            #pragma unroll
            for (int ni = 0; ni < 4; ni++) {
                int c0 = wn * 32 + ni * 8 + g;
                bf[ni][0] = tf32u(b[(kb + t) * 136 + c0]);
                bf[ni][1] = tf32u(b[(kb + t + 4) * 136 + c0]);
            }
            #pragma unroll
            for (int mi = 0; mi < 4; mi++)
                #pragma unroll
                for (int ni = 0; ni < 4; ni++)
                    mma8(acc[mi][ni], af[mi], bf[ni]);
        }
    };

    stage(0);
    stage(1);
    #pragma unroll 1
    for (int s = 0; s < NIT; ++s) {
        cp_wait1();
        __syncthreads();
        if (s + 2 < NIT) stage(s + 2);
        comp(s);
    }

    #pragma unroll
    for (int mi = 0; mi < 4; mi++) {
        int r0 = m0 + wm * 64 + mi * 16 + g;
        #pragma unroll
        for (int ni = 0; ni < 4; ni++) {
            int c0 = n0 + wn * 32 + ni * 8 + t * 2;
            float2 v0, v1;
            v0.x = acc[mi][ni][0] + b2[c0];
            v0.y = acc[mi][ni][1] + b2[c0 + 1];
            v1.x = acc[mi][ni][2] + b2[c0];
            v1.y = acc[mi][ni][3] + b2[c0 + 1];
            *(float2*)(g_hc + (size_t)r0 * C2 + c0)       = v0;
            *(float2*)(g_hc + (size_t)(r0 + 8) * C2 + c0) = v1;
        }
    }
}

// ---------------- 4) GLU + BatchNorm (inference) ----------------------------
__global__ void glu_bn(const float* __restrict__ bg, const float* __restrict__ bb_,
                       const float* __restrict__ bm, const float* __restrict__ bv) {
    int p = blockIdx.x * blockDim.x + threadIdx.x;   // float4 index
    int m = p >> 7;                                  // 128 float4 per row
    int c4 = (p & 127) * 4;
    float4 a  = *(const float4*)(g_hc + (size_t)m * C2 + c4);
    float4 gg = *(const float4*)(g_hc + (size_t)m * C2 + CC + c4);
    float4 o;
    {
        float s = bg[c4] * rsqrtf(bv[c4] + 1e-5f);
        o.x = (a.x * fsigmoid(gg.x) - bm[c4]) * s + bb_[c4];
    }
    {
        float s = bg[c4 + 1] * rsqrtf(bv[c4 + 1] + 1e-5f);
        o.y = (a.y * fsigmoid(gg.y) - bm[c4 + 1]) * s + bb_[c4 + 1];
    }
    {
        float s = bg[c4 + 2] * rsqrtf(bv[c4 + 2] + 1e-5f);
        o.z = (a.z * fsigmoid(gg.z) - bm[c4 + 2]) * s + bb_[c4 + 2];
    }
    {
        float s = bg[c4 + 3] * rsqrtf(bv[c4 + 3] + 1e-5f);
        o.w = (a.w * fsigmoid(gg.w) - bm[c4 + 3]) * s + bb_[c4 + 3];
    }
    *(float4*)(g_h2 + (size_t)m * CC + c4) = o;
}

// ---------------- launch -----------------------------------------------------
extern "C" void kernel_launch(void* const* d_in, const int* in_sizes, int n_in,
                              void* d_out, int out_size) {
    const float* x     = (const float*)d_in[0];
    const float* ln_g  = (const float*)d_in[1];
    const float* ln_b  = (const float*)d_in[2];
    const float* w1    = (const float*)d_in[3];
    const float* b1    = (const float*)d_in[4];
    const float* w2    = (const float*)d_in[5];
    const float* b2    = (const float*)d_in[6];
    const float* bn_g  = (const float*)d_in[7];
    const float* bn_b  = (const float*)d_in[8];
    const float* bn_m  = (const float*)d_in[9];
    const float* bn_v  = (const float*)d_in[10];
    const float* w3    = (const float*)d_in[11];
    const float* b3    = (const float*)d_in[12];
    float* out = (float*)d_out;

    const int smem_gemm = 3 * (128 * 36 + 128 * 36) * 4;   // 110592
    const int smem_conv = 3 * (128 * 36 + 32 * 136) * 4;   // 107520
    cudaFuncSetAttribute(gemm_wt<1, C2, 0, CC>,
                         cudaFuncAttributeMaxDynamicSharedMemorySize, smem_gemm);
    cudaFuncSetAttribute(gemm_wt<0, CC, 1, CC>,
                         cudaFuncAttributeMaxDynamicSharedMemorySize, smem_gemm);
    cudaFuncSetAttribute(conv_gemm,
                         cudaFuncAttributeMaxDynamicSharedMemorySize, smem_conv);

    ln_kernel<<<MTOT, 256>>>(x, ln_g, ln_b);
    gemm_wt<1, C2, 0, CC><<<dim3(MTOT / 128, C2 / 128), 256, smem_gemm>>>(w1, b1, nullptr);
    conv_gemm<<<dim3(MTOT / 128, C2 / 128), 256, smem_conv>>>(w2, b2);
    glu_bn<<<(MTOT * CC / 4) / 256, 256>>>(bn_g, bn_b, bn_m, bn_v);
    gemm_wt<0, CC, 1, CC><<<dim3(MTOT / 128, CC / 128), 256, smem_gemm>>>(w3, b3, out);
}